// round 4
// baseline (speedup 1.0000x reference)
#include <cuda_runtime.h>
#include <stdint.h>

#define NB 8
#define NO 64
#define NT 251
#define NL 48000
#define NT1 3000   /* NL/16  level-1 tiles  */
#define NT2 188    /* ceil(3000/16)         */
#define NT3 12     /* ceil(188/16)          */

// ---------------- device scratch (static, no runtime alloc) ----------------
__device__ float g_A[NB * NO * NT];                       // normalized amps * master
__device__ float g_contrib[(size_t)NB * NO * NL];         // sin(phase)*amp_up per (b,o,l)

// smem floats: rs[NL] ts1[3000] S1[3000] ts2[188] S2[188] ts3[12] S3[12] fs[256] Ar[256]
#define SMEM_FLOATS (NL + 3000 + 3000 + 188 + 188 + 12 + 12 + 256 + 256)
#define SMEM_BYTES  (SMEM_FLOATS * 4)

// exact f32 constants matching the reference's rounding
#define C1F ((float)(2.0 * 3.14159265358979323846 / 48000.0))   /* 2*pi/SR      */
#define C2F ((float)(250.0 / 47999.0))                          /* (T-1)/(L-1)  */
#define PIF ((float)3.14159265358979323846)                     /* f32(np.pi)   */
#define PI64    3.14159265358979323846
#define INV_PI  0.31830988618379067154

// deg-11 odd polynomial for sin on [-pi/2, pi/2], abs err ~1.5e-7 incl. f32 eval
__device__ __forceinline__ float sin_poly(float x) {
    float x2 = __fmul_rn(x, x);
    float p = -2.50521084e-8f;
    p = __fmaf_rn(p, x2, 2.75573192e-6f);
    p = __fmaf_rn(p, x2, -1.98412698e-4f);
    p = __fmaf_rn(p, x2, 8.33333333e-3f);
    p = __fmaf_rn(p, x2, -1.66666667e-1f);
    return __fmaf_rn(__fmul_rn(x, x2), p, x);
}

// ---------------- K1: masked, normalized, master-scaled amplitudes ----------------
__global__ void amps_kernel(const float* __restrict__ f0,
                            const float* __restrict__ master,
                            const float* __restrict__ ov) {
    __shared__ float Ssum[NT];
    int b = blockIdx.x;
    int tid = threadIdx.x;

    for (int t = tid; t < NT; t += blockDim.x) {
        float w = __fmul_rn(f0[b * NT + t], C1F);
        float s = 0.0f;
        for (int o = 0; o < NO; o++) {
            float fsv = __fmul_rn(w, (float)(o + 1));
            float a = (fsv > PIF) ? 0.0f : ov[((size_t)(b * NO + o)) * NT + t];
            s = __fadd_rn(s, a);
        }
        Ssum[t] = s;
    }
    __syncthreads();

    for (int idx = tid; idx < NO * NT; idx += blockDim.x) {
        int o = idx / NT;
        int t = idx - o * NT;
        float w = __fmul_rn(f0[b * NT + t], C1F);
        float fsv = __fmul_rn(w, (float)(o + 1));
        float a = (fsv > PIF) ? 0.0f : ov[((size_t)(b * NO + o)) * NT + t];
        g_A[(b * NO + o) * NT + t] =
            __fmul_rn(__fdiv_rn(a, Ssum[t]), master[b * NT + t]);
    }
}

// ---------------- K2: XLA ReduceWindowRewriter(base=16) blocked scan, then sin*amp ----------------
__global__ void __launch_bounds__(512, 1)
phases_kernel(const float* __restrict__ f0) {
    extern __shared__ float sm[];
    float* rs  = sm;             // [NL]   reduced phases (sign-folded)
    float* ts1 = rs + NL;        // [3000] level-1 tile sums
    float* S1  = ts1 + NT1;      // [3000] inclusive scan of ts1
    float* ts2 = S1 + NT1;       // [188]
    float* S2  = ts2 + NT2;      // [188]
    float* ts3 = S2 + NT2;       // [12]
    float* S3  = ts3 + NT3;      // [12]
    float* fs  = S3 + NT3;       // [256]
    float* Ar  = fs + 256;       // [256]

    int bo = blockIdx.x;
    int b = bo >> 6;
    int o = bo & 63;
    int tid = threadIdx.x;
    const int T = 512;
    float h = (float)(o + 1);

    for (int t = tid; t < NT; t += T) {
        float w = __fmul_rn(f0[b * NT + t], C1F);
        fs[t] = __fmul_rn(w, h);
        Ar[t] = g_A[(b * NO + o) * NT + t];
    }
    __syncthreads();

    // fs_up(l): align_corners linear interp, matches reference formula in f32
    auto fsup = [&](int l) -> float {
        float pos = __fmul_rn((float)l, C2F);
        int i0 = (int)floorf(pos);
        i0 = i0 < 0 ? 0 : (i0 > NT - 2 ? NT - 2 : i0);
        float fr = __fsub_rn(pos, (float)i0);
        return __fadd_rn(__fmul_rn(fs[i0], __fsub_rn(1.0f, fr)),
                         __fmul_rn(fs[i0 + 1], fr));
    };

    // Stage A: level-1 tile sums = sequential left fold of 16 fs_up values
    for (int j = tid; j < NT1; j += T) {
        float s = 0.0f;
        int base = j * 16;
        for (int i = 0; i < 16; i++) s = __fadd_rn(s, fsup(base + i));
        ts1[j] = s;
    }
    __syncthreads();

    // Stage B: level-2 tile sums over ts1 (last tile: 8 real elems; pad-zeros exact)
    for (int k = tid; k < NT2; k += T) {
        float s = 0.0f;
        int bgn = k * 16, end = bgn + 16 < NT1 ? bgn + 16 : NT1;
        for (int i = bgn; i < end; i++) s = __fadd_rn(s, ts1[i]);
        ts2[k] = s;
    }
    __syncthreads();

    // Stage C: level-3 tile sums over ts2, then naive <=16 scan (sequential fold)
    if (tid == 0) {
        for (int p = 0; p < NT3; p++) {
            float s = 0.0f;
            int bgn = p * 16, end = bgn + 16 < NT2 ? bgn + 16 : NT2;
            for (int i = bgn; i < end; i++) s = __fadd_rn(s, ts2[i]);
            ts3[p] = s;
        }
        float r = 0.0f;
        for (int p = 0; p < NT3; p++) { r = __fadd_rn(r, ts3[p]); S3[p] = r; }
    }
    __syncthreads();

    // Stage D: S2[t] = offs3 + fold(ts2[16p..t])
    for (int t = tid; t < NT2; t += T) {
        int p = t >> 4, m = t & 15;
        float s = 0.0f;
        int bgn = p * 16;
        for (int i = 0; i <= m; i++) s = __fadd_rn(s, ts2[bgn + i]);
        float off = p ? S3[p - 1] : 0.0f;
        S2[t] = __fadd_rn(off, s);
    }
    __syncthreads();

    // Stage E: S1[t] = offs2 + fold(ts1[16k..t])
    for (int t = tid; t < NT1; t += T) {
        int k = t >> 4, m = t & 15;
        float s = 0.0f;
        int bgn = k * 16;
        for (int i = 0; i <= m; i++) s = __fadd_rn(s, ts1[bgn + i]);
        float off = k ? S2[k - 1] : 0.0f;
        S1[t] = __fadd_rn(off, s);
    }
    __syncthreads();

    // Stage F1: phase[l] = offs1 + running fold within tile; reduce mod pi -> rs
    for (int j = tid; j < NT1; j += T) {
        float off = j ? S1[j - 1] : 0.0f;
        float run = 0.0f;
        int base = j * 16;
        for (int i = 0; i < 16; i++) {
            run = __fadd_rn(run, fsup(base + i));
            float ph = __fadd_rn(off, run);
            double d = (double)ph;
            double kd = rint(d * INV_PI);
            double r = fma(-kd, PI64, d);
            float rf = (float)r;
            rs[base + i] = (((long long)kd) & 1) ? -rf : rf;  // sin(ph)=sin(rs)
        }
    }
    __syncthreads();

    // Stage F2: coalesced sin*amp -> contrib
    float* outp = g_contrib + (size_t)bo * NL;
    for (int l = tid; l < NL; l += T) {
        float pos = __fmul_rn((float)l, C2F);
        int i0 = (int)floorf(pos);
        i0 = i0 < 0 ? 0 : (i0 > NT - 2 ? NT - 2 : i0);
        float fr = __fsub_rn(pos, (float)i0);
        float amp = __fadd_rn(__fmul_rn(Ar[i0], __fsub_rn(1.0f, fr)),
                              __fmul_rn(Ar[i0 + 1], fr));
        float v = 0.0f;
        if (amp != 0.0f) v = __fmul_rn(sin_poly(rs[l]), amp);
        outp[l] = v;
    }
}

// ---------------- K3: reduce over harmonics ----------------
__global__ void reduce_kernel(float* __restrict__ out) {
    int idx = blockIdx.x * blockDim.x + threadIdx.x;
    if (idx >= NB * NL) return;
    int b = idx / NL;
    int l = idx - b * NL;
    const float* c = g_contrib + (size_t)b * NO * NL + l;
    float s = 0.0f;
#pragma unroll
    for (int o = 0; o < NO; o++) s = __fadd_rn(s, c[(size_t)o * NL]);
    out[idx] = s;
}

// ---------------- launch ----------------
extern "C" void kernel_launch(void* const* d_in, const int* in_sizes, int n_in,
                              void* d_out, int out_size) {
    const float* f0     = (const float*)d_in[0];
    const float* master = (const float*)d_in[1];
    const float* ov     = (const float*)d_in[2];
    float* out = (float*)d_out;

    cudaFuncSetAttribute(phases_kernel,
                         cudaFuncAttributeMaxDynamicSharedMemorySize, SMEM_BYTES);

    amps_kernel<<<NB, 256>>>(f0, master, ov);
    phases_kernel<<<NB * NO, 512, SMEM_BYTES>>>(f0);
    reduce_kernel<<<(NB * NL + 255) / 256, 256>>>(out);
}

// round 6
// speedup vs baseline: 1.8176x; 1.8176x over previous
#include <cuda_runtime.h>
#include <stdint.h>

#define NB 8
#define NO 64
#define NT 251
#define NL 48000
#define NT1 3000   /* NL/16 level-1 tiles */
#define NT2 188    /* ceil(3000/16)       */
#define NT3 12     /* ceil(188/16)        */

// ---------------- device scratch (static, no runtime alloc) ----------------
__device__ float g_contrib[(size_t)NB * NO * NL];   // sin(phase)*amp_up per (b,o,l)

// exact f32 constants matching the reference's rounding
#define C1F ((float)(2.0 * 3.14159265358979323846 / 48000.0))   /* 2*pi/SR     */
#define C2F ((float)(250.0 / 47999.0))                          /* (T-1)/(L-1) */
#define PIF ((float)3.14159265358979323846)                     /* f32(np.pi)  */

// Cody-Waite split of pi; with k <= 2^18 the first three FMA steps are exact.
#define PI_A 3.140625f                  /* 7-bit head                   */
#define PI_B 9.65118408203125e-4f       /* next 8 bits (506*2^-19)      */
#define PI_C 2.5331974029541016e-6f     /* next 8 bits (340*2^-27)      */
#define PI_D 1.9841872e-9f              /* f32 of remaining tail        */
#define INVPI_F 0.31830988618379067154f

// deg-11 odd minimax sin on |x| <~ 1.6, abs err ~2e-7 incl. f32 eval
__device__ __forceinline__ float sin_poly(float x) {
    float x2 = __fmul_rn(x, x);
    float p = -2.50521084e-8f;
    p = __fmaf_rn(p, x2, 2.75573192e-6f);
    p = __fmaf_rn(p, x2, -1.98412698e-4f);
    p = __fmaf_rn(p, x2, 8.33333333e-3f);
    p = __fmaf_rn(p, x2, -1.66666667e-1f);
    return __fmaf_rn(__fmul_rn(x, x2), p, x);
}

// ---------------- K1: fused amps + XLA blocked scan + sin*amp ----------------
__global__ void __launch_bounds__(256)
phases_kernel(const float* __restrict__ f0,
              const float* __restrict__ master,
              const float* __restrict__ ov) {
    __shared__ float buf[3392];     // union: ts1[0..3000) ts2@3000 S2@3188 S3@3376
    __shared__ float S1[NT1];
    __shared__ float fs[256];
    __shared__ float Ar[256];
    float* ts1 = buf;
    float* ts2 = buf + 3000;
    float* S2  = buf + 3188;
    float* S3  = buf + 3376;

    int bo = blockIdx.x;
    int b = bo >> 6;
    int o = bo & 63;
    int tid = threadIdx.x;
    float h = (float)(o + 1);

    // fused amps: per-frame mask + normalize + master scale (same f32 op order as before)
    for (int t = tid; t < NT; t += 256) {
        float w = __fmul_rn(f0[b * NT + t], C1F);
        float s = 0.0f;
        for (int oo = 0; oo < NO; oo++) {
            float fsv = __fmul_rn(w, (float)(oo + 1));
            float a = (fsv > PIF) ? 0.0f : ov[((size_t)(b * NO + oo)) * NT + t];
            s = __fadd_rn(s, a);
        }
        float fso = __fmul_rn(w, h);
        fs[t] = fso;
        float ao = (fso > PIF) ? 0.0f : ov[((size_t)(b * NO + o)) * NT + t];
        Ar[t] = __fmul_rn(__fdiv_rn(ao, s), master[b * NT + t]);
    }
    __syncthreads();

    // fs_up(l): align_corners linear interp, bit-identical to the passing version
    auto fsup = [&](int l) -> float {
        float pos = __fmul_rn((float)l, C2F);
        int i0 = (int)floorf(pos);
        i0 = i0 < 0 ? 0 : (i0 > NT - 2 ? NT - 2 : i0);
        float fr = __fsub_rn(pos, (float)i0);
        return __fadd_rn(__fmul_rn(fs[i0], __fsub_rn(1.0f, fr)),
                         __fmul_rn(fs[i0 + 1], fr));
    };

    // Stage A: level-1 tile sums (fold of 16)
    for (int j = tid; j < NT1; j += 256) {
        float s = 0.0f;
        int base = j * 16;
#pragma unroll 4
        for (int i = 0; i < 16; i++) s = __fadd_rn(s, fsup(base + i));
        ts1[j] = s;
    }
    __syncthreads();

    // Stage B: level-2 tile sums
    for (int k = tid; k < NT2; k += 256) {
        float s = 0.0f;
        int bgn = k * 16, end = bgn + 16 < NT1 ? bgn + 16 : NT1;
        for (int i = bgn; i < end; i++) s = __fadd_rn(s, ts1[i]);
        ts2[k] = s;
    }
    __syncthreads();

    // Stage C: level-3 tile sums (parallel over 12), then tiny serial scan
    if (tid < NT3) {
        float s = 0.0f;
        int bgn = tid * 16, end = bgn + 16 < NT2 ? bgn + 16 : NT2;
        for (int i = bgn; i < end; i++) s = __fadd_rn(s, ts2[i]);
        S3[tid] = s;
    }
    __syncthreads();
    if (tid == 0) {
        float r = 0.0f;
        for (int p = 0; p < NT3; p++) { r = __fadd_rn(r, S3[p]); S3[p] = r; }
    }
    __syncthreads();

    // Stage D: S2[t] = offs3 + fold(ts2[16p..t])
    if (tid < NT2) {
        int t = tid, p = t >> 4, m = t & 15;
        float s = 0.0f;
        int bgn = p * 16;
        for (int i = 0; i <= m; i++) s = __fadd_rn(s, ts2[bgn + i]);
        float off = p ? S3[p - 1] : 0.0f;
        S2[t] = __fadd_rn(off, s);
    }
    __syncthreads();

    // Stage E: S1[t] = offs2 + fold(ts1[16k..t])
    for (int t = tid; t < NT1; t += 256) {
        int k = t >> 4, m = t & 15;
        float s = 0.0f;
        int bgn = k * 16;
        for (int i = 0; i <= m; i++) s = __fadd_rn(s, ts1[bgn + i]);
        float off = k ? S2[k - 1] : 0.0f;
        S1[t] = __fadd_rn(off, s);
    }
    __syncthreads();

    // Stage F (fused): phase, f32 Cody-Waite mod-pi, sin, amp, float4 store
    float* outp = g_contrib + (size_t)bo * NL;
    for (int j = tid; j < NT1; j += 256) {
        float off = j ? S1[j - 1] : 0.0f;
        float run = 0.0f;
        int base = j * 16;
#pragma unroll
        for (int q = 0; q < 4; q++) {
            float vv[4];
#pragma unroll
            for (int i = 0; i < 4; i++) {
                int l = base + q * 4 + i;
                float pos = __fmul_rn((float)l, C2F);
                int i0 = (int)floorf(pos);
                i0 = i0 < 0 ? 0 : (i0 > NT - 2 ? NT - 2 : i0);
                float fr = __fsub_rn(pos, (float)i0);
                float omf = __fsub_rn(1.0f, fr);
                float f = __fadd_rn(__fmul_rn(fs[i0], omf), __fmul_rn(fs[i0 + 1], fr));
                run = __fadd_rn(run, f);
                float ph = __fadd_rn(off, run);
                float amp = __fadd_rn(__fmul_rn(Ar[i0], omf), __fmul_rn(Ar[i0 + 1], fr));
                float v = 0.0f;
                if (amp != 0.0f) {
                    float kf = rintf(__fmul_rn(ph, INVPI_F));
                    float r = __fmaf_rn(-kf, PI_A, ph);   // exact
                    r = __fmaf_rn(-kf, PI_B, r);          // exact
                    r = __fmaf_rn(-kf, PI_C, r);          // ~2^-24
                    r = __fmaf_rn(-kf, PI_D, r);          // ~2^-24
                    float sv = sin_poly(r);               // sin(ph)=(-1)^k sin(r)
                    v = ((int)kf & 1) ? __fmul_rn(-sv, amp) : __fmul_rn(sv, amp);
                }
                vv[i] = v;
            }
            float4 v4;
            v4.x = vv[0]; v4.y = vv[1]; v4.z = vv[2]; v4.w = vv[3];
            *reinterpret_cast<float4*>(outp + base + q * 4) = v4;
        }
    }
}

// ---------------- K2: vectorized reduce over harmonics ----------------
__global__ void reduce_kernel(float* __restrict__ out) {
    const int NL4 = NL / 4;
    int idx = blockIdx.x * blockDim.x + threadIdx.x;
    if (idx >= NB * NL4) return;
    int b = idx / NL4;
    int l4 = idx - b * NL4;
    const float4* c = reinterpret_cast<const float4*>(g_contrib)
                      + (size_t)b * NO * NL4 + l4;
    float4 s = make_float4(0.f, 0.f, 0.f, 0.f);
#pragma unroll 8
    for (int o = 0; o < NO; o++) {
        float4 v = c[(size_t)o * NL4];
        s.x = __fadd_rn(s.x, v.x);
        s.y = __fadd_rn(s.y, v.y);
        s.z = __fadd_rn(s.z, v.z);
        s.w = __fadd_rn(s.w, v.w);
    }
    reinterpret_cast<float4*>(out)[idx] = s;
}

// ---------------- launch ----------------
extern "C" void kernel_launch(void* const* d_in, const int* in_sizes, int n_in,
                              void* d_out, int out_size) {
    const float* f0     = (const float*)d_in[0];
    const float* master = (const float*)d_in[1];
    const float* ov     = (const float*)d_in[2];
    float* out = (float*)d_out;

    phases_kernel<<<NB * NO, 256>>>(f0, master, ov);
    reduce_kernel<<<(NB * (NL / 4) + 255) / 256, 256>>>(out);
}

// round 7
// speedup vs baseline: 1.9930x; 1.0965x over previous
#include <cuda_runtime.h>
#include <stdint.h>

#define NB 8
#define NO 64
#define NT 251
#define NL 48000
#define NT1 3000   /* NL/16 level-1 tiles */
#define NT2 188
#define NT3 12
#define TPB_CHUNK 64          /* tiles per K2 block */
#define NCHUNK 47             /* ceil(3000/64) */

// ---------------- device scratch (static, no runtime alloc) ----------------
__device__ float g_S1[NB * NO * NT1];   // per-(b,o) inclusive tile-prefix sums, 6.1MB
__device__ float g_A[NB * NO * NT];     // normalized amps * master

// exact f32 constants matching the reference's rounding
#define C1F ((float)(2.0 * 3.14159265358979323846 / 48000.0))
#define C2F ((float)(250.0 / 47999.0))
#define PIF ((float)3.14159265358979323846)

// Cody-Waite split of pi; k <= 2^18 keeps the first steps exact.
#define PI_A 3.140625f
#define PI_B 9.65118408203125e-4f
#define PI_C 2.5331974029541016e-6f
#define PI_D 1.9841872e-9f
#define INVPI_F 0.31830988618379067154f

__device__ __forceinline__ float sin_poly(float x) {
    float x2 = __fmul_rn(x, x);
    float p = -2.50521084e-8f;
    p = __fmaf_rn(p, x2, 2.75573192e-6f);
    p = __fmaf_rn(p, x2, -1.98412698e-4f);
    p = __fmaf_rn(p, x2, 8.33333333e-3f);
    p = __fmaf_rn(p, x2, -1.66666667e-1f);
    return __fmaf_rn(__fmul_rn(x, x2), p, x);
}

// ---------------- K1: amps + XLA blocked scan -> S1, Ar (per b,o) ----------------
__global__ void __launch_bounds__(256)
scan_kernel(const float* __restrict__ f0,
            const float* __restrict__ master,
            const float* __restrict__ ov) {
    __shared__ float buf[3392];     // ts1[0..3000) ts2@3000 S2@3188 S3@3376
    __shared__ float S1[NT1];
    __shared__ float fs[256];
    __shared__ float Ar[256];
    float* ts1 = buf;
    float* ts2 = buf + 3000;
    float* S2  = buf + 3188;
    float* S3  = buf + 3376;

    int bo = blockIdx.x;
    int b = bo >> 6;
    int o = bo & 63;
    int tid = threadIdx.x;
    float h = (float)(o + 1);

    // amps: per-frame mask + normalize + master scale (identical f32 op order)
    for (int t = tid; t < NT; t += 256) {
        float w = __fmul_rn(f0[b * NT + t], C1F);
        float s = 0.0f;
        for (int oo = 0; oo < NO; oo++) {
            float fsv = __fmul_rn(w, (float)(oo + 1));
            float a = (fsv > PIF) ? 0.0f : ov[((size_t)(b * NO + oo)) * NT + t];
            s = __fadd_rn(s, a);
        }
        float fso = __fmul_rn(w, h);
        fs[t] = fso;
        float ao = (fso > PIF) ? 0.0f : ov[((size_t)(b * NO + o)) * NT + t];
        float ar = __fmul_rn(__fdiv_rn(ao, s), master[b * NT + t]);
        Ar[t] = ar;
        g_A[bo * NT + t] = ar;
    }
    __syncthreads();

    auto fsup = [&](int l) -> float {
        float pos = __fmul_rn((float)l, C2F);
        int i0 = (int)floorf(pos);
        i0 = i0 < 0 ? 0 : (i0 > NT - 2 ? NT - 2 : i0);
        float fr = __fsub_rn(pos, (float)i0);
        return __fadd_rn(__fmul_rn(fs[i0], __fsub_rn(1.0f, fr)),
                         __fmul_rn(fs[i0 + 1], fr));
    };

    // Stage A
    for (int j = tid; j < NT1; j += 256) {
        float s = 0.0f;
        int base = j * 16;
#pragma unroll 4
        for (int i = 0; i < 16; i++) s = __fadd_rn(s, fsup(base + i));
        ts1[j] = s;
    }
    __syncthreads();
    // Stage B
    for (int k = tid; k < NT2; k += 256) {
        float s = 0.0f;
        int bgn = k * 16, end = bgn + 16 < NT1 ? bgn + 16 : NT1;
        for (int i = bgn; i < end; i++) s = __fadd_rn(s, ts1[i]);
        ts2[k] = s;
    }
    __syncthreads();
    // Stage C
    if (tid < NT3) {
        float s = 0.0f;
        int bgn = tid * 16, end = bgn + 16 < NT2 ? bgn + 16 : NT2;
        for (int i = bgn; i < end; i++) s = __fadd_rn(s, ts2[i]);
        S3[tid] = s;
    }
    __syncthreads();
    if (tid == 0) {
        float r = 0.0f;
        for (int p = 0; p < NT3; p++) { r = __fadd_rn(r, S3[p]); S3[p] = r; }
    }
    __syncthreads();
    // Stage D
    if (tid < NT2) {
        int t = tid, p = t >> 4, m = t & 15;
        float s = 0.0f;
        int bgn = p * 16;
        for (int i = 0; i <= m; i++) s = __fadd_rn(s, ts2[bgn + i]);
        float off = p ? S3[p - 1] : 0.0f;
        S2[t] = __fadd_rn(off, s);
    }
    __syncthreads();
    // Stage E + write-out
    for (int t = tid; t < NT1; t += 256) {
        int k = t >> 4, m = t & 15;
        float s = 0.0f;
        int bgn = k * 16;
        for (int i = 0; i <= m; i++) s = __fadd_rn(s, ts1[bgn + i]);
        float off = k ? S2[k - 1] : 0.0f;
        g_S1[bo * NT1 + t] = __fadd_rn(off, s);
    }
}

// ---------------- K2: fused synthesis + harmonic reduction ----------------
// block = (b, 64-tile chunk). thread: tile_local = tid>>2, og = tid&3 (16 o's).
__global__ void __launch_bounds__(256)
synth_kernel(const float* __restrict__ f0, float* __restrict__ out) {
    __shared__ float S1s[NO * (TPB_CHUNK + 1)];   // [o][jj], jj = j-(j0-1), 16.6KB
    __shared__ float Ars[NO * 9];                 // [o][f-fb], 2.3KB
    __shared__ float ws[16];                      // w at frames fb..fb+8

    int blk = blockIdx.x;
    int b = blk / NCHUNK;
    int chunk = blk - b * NCHUNK;
    int j0 = chunk * TPB_CHUNK;
    int tid = threadIdx.x;

    // frame base for this chunk
    int l0 = j0 * 16;
    float pos0 = __fmul_rn((float)l0, C2F);
    int fb = (int)floorf(pos0);
    fb = fb < 0 ? 0 : (fb > NT - 2 ? NT - 2 : fb);

    // stage w (frames fb..fb+8)
    if (tid < 9) {
        int f = fb + tid;
        ws[tid] = (f < NT) ? __fmul_rn(f0[b * NT + f], C1F) : 0.0f;
    }
    // stage Ar slice
    for (int idx = tid; idx < NO * 9; idx += 256) {
        int o = idx / 9, ff = idx - o * 9;
        int f = fb + ff;
        Ars[idx] = (f < NT) ? g_A[(b * NO + o) * NT + f] : 0.0f;
    }
    // stage S1 slice: jj 0..64 -> j = j0-1+jj
    for (int idx = tid; idx < NO * (TPB_CHUNK + 1); idx += 256) {
        int o = idx / (TPB_CHUNK + 1), jj = idx - o * (TPB_CHUNK + 1);
        int j = j0 - 1 + jj;
        S1s[idx] = (j >= 0 && j < NT1) ? g_S1[(b * NO + o) * NT1 + j] : 0.0f;
    }
    __syncthreads();

    int tile_local = tid >> 2;
    int og = tid & 3;
    int obase = og << 4;
    int j = j0 + tile_local;
    bool valid = (j < NT1);

    // skip whole o-group if all its staged amps are zero (aliased harmonics)
    bool anyamp = false;
    for (int oo = 0; oo < 16; oo++)
        for (int ff = 0; ff < 9; ff++)
            anyamp |= (Ars[(obase + oo) * 9 + ff] != 0.0f);
    bool active = valid && anyamp;

    float off[16], run[16], hv[16];
#pragma unroll
    for (int oo = 0; oo < 16; oo++) {
        off[oo] = (j == 0) ? 0.0f
                : S1s[(obase + oo) * (TPB_CHUNK + 1) + tile_local];
        run[oo] = 0.0f;
        hv[oo] = (float)(obase + oo + 1);
    }

    int lbase = j * 16;
#pragma unroll 1
    for (int i = 0; i < 16; i++) {
        float accs = 0.0f;
        if (active) {
            int l = lbase + i;
            float pos = __fmul_rn((float)l, C2F);
            int i0 = (int)floorf(pos);
            i0 = i0 < 0 ? 0 : (i0 > NT - 2 ? NT - 2 : i0);
            float fr = __fsub_rn(pos, (float)i0);
            float omf = __fsub_rn(1.0f, fr);
            int fi = i0 - fb;
            float w0 = ws[fi], w1 = ws[fi + 1];
#pragma unroll
            for (int oo = 0; oo < 16; oo++) {
                float h = hv[oo];
                float f = __fadd_rn(__fmul_rn(__fmul_rn(w0, h), omf),
                                    __fmul_rn(__fmul_rn(w1, h), fr));
                run[oo] = __fadd_rn(run[oo], f);
                float ph = __fadd_rn(off[oo], run[oo]);
                float a0 = Ars[(obase + oo) * 9 + fi];
                float a1 = Ars[(obase + oo) * 9 + fi + 1];
                float amp = __fadd_rn(__fmul_rn(a0, omf), __fmul_rn(a1, fr));
                if (amp != 0.0f) {
                    float kf = rintf(__fmul_rn(ph, INVPI_F));
                    float r = __fmaf_rn(-kf, PI_A, ph);
                    r = __fmaf_rn(-kf, PI_B, r);
                    r = __fmaf_rn(-kf, PI_C, r);
                    r = __fmaf_rn(-kf, PI_D, r);
                    float sv = sin_poly(r);
                    float v = ((int)kf & 1) ? __fmul_rn(-sv, amp)
                                            : __fmul_rn(sv, amp);
                    accs = __fadd_rn(accs, v);
                }
            }
        }
        // deterministic cross-og reduction (lanes differ only in og bits)
        accs = __fadd_rn(accs, __shfl_xor_sync(0xffffffffu, accs, 1));
        accs = __fadd_rn(accs, __shfl_xor_sync(0xffffffffu, accs, 2));
        if (og == 0 && valid) out[b * NL + lbase + i] = accs;
    }
}

// ---------------- launch ----------------
extern "C" void kernel_launch(void* const* d_in, const int* in_sizes, int n_in,
                              void* d_out, int out_size) {
    const float* f0     = (const float*)d_in[0];
    const float* master = (const float*)d_in[1];
    const float* ov     = (const float*)d_in[2];
    float* out = (float*)d_out;

    scan_kernel<<<NB * NO, 256>>>(f0, master, ov);
    synth_kernel<<<NB * NCHUNK, 256>>>(f0, out);
}

// round 8
// speedup vs baseline: 2.0449x; 1.0261x over previous
#include <cuda_runtime.h>
#include <stdint.h>

#define NB 8
#define NO 64
#define NT 251
#define NL 48000
#define NT1 3000   /* NL/16 level-1 tiles */
#define NT2 188
#define NT3 12
#define TPB_CHUNK 32          /* tiles per K2 block */
#define NCHUNK 94             /* ceil(3000/32) */
#define NOG 8                 /* o-groups per tile */
#define OPG 8                 /* harmonics per group */
#define FR 6                  /* staged frames per chunk */

// ---------------- device scratch (static, no runtime alloc) ----------------
__device__ float g_S1[NB * NO * NT1];   // per-(b,o) inclusive tile-prefix sums
__device__ float g_A[NB * NO * NT];     // normalized amps * master

// exact f32 constants matching the reference's rounding
#define C1F ((float)(2.0 * 3.14159265358979323846 / 48000.0))
#define C2F ((float)(250.0 / 47999.0))
#define PIF ((float)3.14159265358979323846)

// Cody-Waite split of pi; k <= 2^18 keeps the first steps exact.
#define PI_A 3.140625f
#define PI_B 9.65118408203125e-4f
#define PI_C 2.5331974029541016e-6f
#define PI_D 1.9841872e-9f
#define INVPI_F 0.31830988618379067154f

__device__ __forceinline__ float sin_poly(float x) {
    float x2 = __fmul_rn(x, x);
    float p = -2.50521084e-8f;
    p = __fmaf_rn(p, x2, 2.75573192e-6f);
    p = __fmaf_rn(p, x2, -1.98412698e-4f);
    p = __fmaf_rn(p, x2, 8.33333333e-3f);
    p = __fmaf_rn(p, x2, -1.66666667e-1f);
    return __fmaf_rn(__fmul_rn(x, x2), p, x);
}

// ---------------- K1: amps + XLA blocked scan -> S1, Ar (per b,o) ----------------
__global__ void __launch_bounds__(512)
scan_kernel(const float* __restrict__ f0,
            const float* __restrict__ master,
            const float* __restrict__ ov) {
    __shared__ float buf[3392];     // ts1[0..3000) ts2@3000 S2@3188 S3@3376
    __shared__ float fs[256];
    float* ts1 = buf;
    float* ts2 = buf + 3000;
    float* S2  = buf + 3188;
    float* S3  = buf + 3376;

    int bo = blockIdx.x;
    int b = bo >> 6;
    int o = bo & 63;
    int tid = threadIdx.x;
    const int T = 512;
    float h = (float)(o + 1);

    // amps: per-frame mask + normalize + master scale (identical f32 op order)
    if (tid < NT) {
        int t = tid;
        float w = __fmul_rn(f0[b * NT + t], C1F);
        float s = 0.0f;
        for (int oo = 0; oo < NO; oo++) {
            float fsv = __fmul_rn(w, (float)(oo + 1));
            float a = (fsv > PIF) ? 0.0f : ov[((size_t)(b * NO + oo)) * NT + t];
            s = __fadd_rn(s, a);
        }
        float fso = __fmul_rn(w, h);
        fs[t] = fso;
        float ao = (fso > PIF) ? 0.0f : ov[((size_t)(b * NO + o)) * NT + t];
        g_A[bo * NT + t] = __fmul_rn(__fdiv_rn(ao, s), master[b * NT + t]);
    }
    __syncthreads();

    auto fsup = [&](int l) -> float {
        float pos = __fmul_rn((float)l, C2F);
        int i0 = (int)floorf(pos);
        i0 = i0 < 0 ? 0 : (i0 > NT - 2 ? NT - 2 : i0);
        float fr = __fsub_rn(pos, (float)i0);
        return __fadd_rn(__fmul_rn(fs[i0], __fsub_rn(1.0f, fr)),
                         __fmul_rn(fs[i0 + 1], fr));
    };

    // Stage A: level-1 tile sums
    for (int j = tid; j < NT1; j += T) {
        float s = 0.0f;
        int base = j * 16;
#pragma unroll 4
        for (int i = 0; i < 16; i++) s = __fadd_rn(s, fsup(base + i));
        ts1[j] = s;
    }
    __syncthreads();
    // Stage B
    if (tid < NT2) {
        int k = tid;
        float s = 0.0f;
        int bgn = k * 16, end = bgn + 16 < NT1 ? bgn + 16 : NT1;
        for (int i = bgn; i < end; i++) s = __fadd_rn(s, ts1[i]);
        ts2[k] = s;
    }
    __syncthreads();
    // Stage C
    if (tid < NT3) {
        float s = 0.0f;
        int bgn = tid * 16, end = bgn + 16 < NT2 ? bgn + 16 : NT2;
        for (int i = bgn; i < end; i++) s = __fadd_rn(s, ts2[i]);
        S3[tid] = s;
    }
    __syncthreads();
    if (tid == 0) {
        float r = 0.0f;
        for (int p = 0; p < NT3; p++) { r = __fadd_rn(r, S3[p]); S3[p] = r; }
    }
    __syncthreads();
    // Stage D
    if (tid < NT2) {
        int t = tid, p = t >> 4, m = t & 15;
        float s = 0.0f;
        int bgn = p * 16;
        for (int i = 0; i <= m; i++) s = __fadd_rn(s, ts2[bgn + i]);
        float off = p ? S3[p - 1] : 0.0f;
        S2[t] = __fadd_rn(off, s);
    }
    __syncthreads();
    // Stage E + write-out
    for (int t = tid; t < NT1; t += T) {
        int k = t >> 4, m = t & 15;
        float s = 0.0f;
        int bgn = k * 16;
        for (int i = 0; i <= m; i++) s = __fadd_rn(s, ts1[bgn + i]);
        float off = k ? S2[k - 1] : 0.0f;
        g_S1[bo * NT1 + t] = __fadd_rn(off, s);
    }
}

// ---------------- K2: fused synthesis + harmonic reduction ----------------
// block = (b, 32-tile chunk). thread: tile_local = tid>>3, og = tid&7 (8 o's).
__global__ void __launch_bounds__(256)
synth_kernel(const float* __restrict__ f0, float* __restrict__ out) {
    __shared__ float S1s[NO * (TPB_CHUNK + 1)];   // [o][jj], jj = j-(j0-1)
    __shared__ float Ars[NO * FR];                // [o][f-fb]
    __shared__ float ws[FR];                      // w at frames fb..fb+FR-1

    int blk = blockIdx.x;
    int b = blk / NCHUNK;
    int chunk = blk - b * NCHUNK;
    int j0 = chunk * TPB_CHUNK;
    int tid = threadIdx.x;

    // frame base for this chunk
    int l0 = j0 * 16;
    float pos0 = __fmul_rn((float)l0, C2F);
    int fb = (int)floorf(pos0);
    fb = fb < 0 ? 0 : (fb > NT - 2 ? NT - 2 : fb);

    if (tid < FR) {
        int f = fb + tid;
        ws[tid] = (f < NT) ? __fmul_rn(f0[b * NT + f], C1F) : 0.0f;
    }
    for (int idx = tid; idx < NO * FR; idx += 256) {
        int o = idx / FR, ff = idx - o * FR;
        int f = fb + ff;
        Ars[idx] = (f < NT) ? g_A[(b * NO + o) * NT + f] : 0.0f;
    }
    for (int idx = tid; idx < NO * (TPB_CHUNK + 1); idx += 256) {
        int o = idx / (TPB_CHUNK + 1), jj = idx - o * (TPB_CHUNK + 1);
        int j = j0 - 1 + jj;
        S1s[idx] = (j >= 0 && j < NT1) ? g_S1[(b * NO + o) * NT1 + j] : 0.0f;
    }
    __syncthreads();

    int tile_local = tid >> 3;
    int og = tid & (NOG - 1);
    int obase = og * OPG;
    int j = j0 + tile_local;
    bool valid = (j < NT1);

    // skip whole o-group if all its staged amps are zero (aliased harmonics)
    bool anyamp = false;
    for (int oo = 0; oo < OPG; oo++)
        for (int ff = 0; ff < FR; ff++)
            anyamp |= (Ars[(obase + oo) * FR + ff] != 0.0f);
    bool active = valid && anyamp;

    float off[OPG], run[OPG], hv[OPG];
#pragma unroll
    for (int oo = 0; oo < OPG; oo++) {
        off[oo] = (j == 0) ? 0.0f
                : S1s[(obase + oo) * (TPB_CHUNK + 1) + tile_local];
        run[oo] = 0.0f;
        hv[oo] = (float)(obase + oo + 1);
    }

    int lbase = j * 16;
#pragma unroll 1
    for (int i = 0; i < 16; i++) {
        float accs = 0.0f;
        if (active) {
            int l = lbase + i;
            float pos = __fmul_rn((float)l, C2F);
            int i0 = (int)floorf(pos);
            i0 = i0 < 0 ? 0 : (i0 > NT - 2 ? NT - 2 : i0);
            float fr = __fsub_rn(pos, (float)i0);
            float omf = __fsub_rn(1.0f, fr);
            int fi = i0 - fb;
            float w0 = ws[fi], w1 = ws[fi + 1];
#pragma unroll
            for (int oo = 0; oo < OPG; oo++) {
                float h = hv[oo];
                float f = __fadd_rn(__fmul_rn(__fmul_rn(w0, h), omf),
                                    __fmul_rn(__fmul_rn(w1, h), fr));
                run[oo] = __fadd_rn(run[oo], f);
                float ph = __fadd_rn(off[oo], run[oo]);
                float a0 = Ars[(obase + oo) * FR + fi];
                float a1 = Ars[(obase + oo) * FR + fi + 1];
                float amp = __fadd_rn(__fmul_rn(a0, omf), __fmul_rn(a1, fr));
                if (amp != 0.0f) {
                    float kf = rintf(__fmul_rn(ph, INVPI_F));
                    float r = __fmaf_rn(-kf, PI_A, ph);
                    r = __fmaf_rn(-kf, PI_B, r);
                    r = __fmaf_rn(-kf, PI_C, r);
                    r = __fmaf_rn(-kf, PI_D, r);
                    float sv = sin_poly(r);
                    float v = ((int)kf & 1) ? __fmul_rn(-sv, amp)
                                            : __fmul_rn(sv, amp);
                    accs = __fadd_rn(accs, v);
                }
            }
        }
        // deterministic cross-og reduction (lanes differ only in og bits 0..2)
        accs = __fadd_rn(accs, __shfl_xor_sync(0xffffffffu, accs, 1));
        accs = __fadd_rn(accs, __shfl_xor_sync(0xffffffffu, accs, 2));
        accs = __fadd_rn(accs, __shfl_xor_sync(0xffffffffu, accs, 4));
        if (og == 0 && valid) out[b * NL + lbase + i] = accs;
    }
}

// ---------------- launch ----------------
extern "C" void kernel_launch(void* const* d_in, const int* in_sizes, int n_in,
                              void* d_out, int out_size) {
    const float* f0     = (const float*)d_in[0];
    const float* master = (const float*)d_in[1];
    const float* ov     = (const float*)d_in[2];
    float* out = (float*)d_out;

    scan_kernel<<<NB * NO, 512>>>(f0, master, ov);
    synth_kernel<<<NB * NCHUNK, 256>>>(f0, out);
}